// round 11
// baseline (speedup 1.0000x reference)
#include <cuda_runtime.h>
#include <math.h>
#include <stdint.h>

#define B_    256
#define NIN_  6912
#define SLOTS 8

#define NPB   24            // n per block
#define NST   2             // n per stage
#define NSTG  (NPB / NST)   // 12 stages
#define NBUF  3

typedef unsigned long long ull;

#define FFMA2(d, a, b, c) \
    asm("fma.rn.f32x2 %0, %1, %2, %3;" : "=l"(d) : "l"(a), "l"(b), "l"(c))
#define FMUL2(d, a, b) \
    asm("mul.rn.f32x2 %0, %1, %2;" : "=l"(d) : "l"(a), "l"(b))
#define PACK2(d, lo, hi) \
    asm("mov.b64 %0, {%1, %2};" : "=l"(d) : "f"(lo), "f"(hi))
#define UNPACK2(lo, hi, v) \
    asm("mov.b64 {%0, %1}, %2;" : "=f"(lo), "=f"(hi) : "l"(v))

__device__ __forceinline__ uint32_t s2u(const void* p) {
    return (uint32_t)__cvta_generic_to_shared(p);
}
__device__ __forceinline__ void cp16(const void* sdst, const void* gsrc) {
    asm volatile("cp.async.cg.shared.global [%0], [%1], 16;"
                 :: "r"(s2u(sdst)), "l"(gsrc) : "memory");
}
#define CP_COMMIT() asm volatile("cp.async.commit_group;" ::: "memory")
template <int N>
__device__ __forceinline__ void cp_wait() {
    asm volatile("cp.async.wait_group %0;" :: "n"(N) : "memory");
}

// Scratch: s1/s2 transposed [slot][k][b] (k=j*16+e); v1 [b][k].
__device__ float g_s1[SLOTS * B_ * 32];
__device__ float g_s2[SLOTS * B_ * 32];
__device__ __align__(16) float g_v1[B_ * 32];

__global__ void zero_kernel() {
    int i = blockIdx.x * blockDim.x + threadIdx.x;
    if (i < SLOTS * B_ * 32) { g_s1[i] = 0.0f; g_s2[i] = 0.0f; }
}

__device__ __forceinline__ void squash16(const float* s, float* v) {
    float n2 = 0.0f;
#pragma unroll
    for (int e = 0; e < 16; ++e) n2 = fmaf(s[e], s[e], n2);
    float f = n2 / ((1.0f + n2) * sqrtf(n2 + 1e-9f));
#pragma unroll
    for (int e = 0; e < 16; ++e) v[e] = s[e] * f;
}

// W stage mapping: 128 float4 per stage, coalesced gmem reads.
// Wd[buf][nl][e][h][j]; strides (f4): j=1, h=2, e=4, nl=64.
#define STAGE_W(Wd, buf, n0, f)                                               \
    do {                                                                      \
        int h_ = (f) & 1, e_ = ((f) >> 1) & 15, jj_ = ((f) >> 5) & 1,         \
            nl_ = ((f) >> 6) & 1;                                             \
        cp16(&Wd[buf][nl_][e_][h_][jj_],                                      \
             Wg + ((size_t)(jj_ * NIN_ + (n0) + nl_) * 16 + e_) * 2 + h_);    \
    } while (0)

// ======================= Pass 1 =======================
// 256 threads = 8 warps. Lane: j = l&1, eh = (l>>1)&1, bq = l>>2.
// Thread: capsule j, e = 2*ei+eh (ei 0..7), 2 b's: lb_i = w*16 + i*8 + bq.
// Block covers 128 b; grid = (288, 2). 3 blocks/SM -> 24 warps.
#define P1_THR 256

__global__ __launch_bounds__(P1_THR, 3) void pass1_kernel(const float4* __restrict__ X,
                                                          const float4* __restrict__ Wg) {
    __shared__ float4 Wd[NBUF][NST][16][2][2];
    __shared__ float4 xs[NBUF][128][NST * 2 + 1];   // row = 5 f4 = 80B

    const int tid  = threadIdx.x;
    const int w    = tid >> 5;
    const int lane = tid & 31;
    const int j    = lane & 1;
    const int eh   = (lane >> 1) & 1;
    const int bq   = lane >> 2;
    const int gbb  = blockIdx.y * 128;
    const int nbase = blockIdx.x * NPB;

    const int lb0 = w * 16 + bq;
    const int lb1 = lb0 + 8;

    ull acc[2][8];                      // [b][ei], d-pair packed
    ull zero; PACK2(zero, 0.0f, 0.0f);
#pragma unroll
    for (int i = 0; i < 2; ++i)
#pragma unroll
        for (int ei = 0; ei < 8; ++ei) acc[i][ei] = zero;

    auto issue = [&](int s) {
        const int buf = s % NBUF;
        const int n0  = nbase + s * NST;
        if (tid < 128) STAGE_W(Wd, buf, n0, tid);
#pragma unroll
        for (int it = 0; it < 2; ++it) {   // x: 512 f4, 2 per thread
            int f = it * P1_THR + tid;
            int bl = f >> 2, q = f & 3;
            cp16(&xs[buf][bl][q],
                 X + ((size_t)(gbb + bl) * NIN_ + n0 + (q >> 1)) * 2 + (q & 1));
        }
        CP_COMMIT();
    };

    auto compute = [&](int s) {
        const int buf = s % NBUF;
#pragma unroll
        for (int nl = 0; nl < NST; ++nl) {
            ulonglong2 xv[2][2];
            xv[0][0] = *reinterpret_cast<const ulonglong2*>(&xs[buf][lb0][nl * 2]);
            xv[0][1] = *reinterpret_cast<const ulonglong2*>(&xs[buf][lb0][nl * 2 + 1]);
            xv[1][0] = *reinterpret_cast<const ulonglong2*>(&xs[buf][lb1][nl * 2]);
            xv[1][1] = *reinterpret_cast<const ulonglong2*>(&xs[buf][lb1][nl * 2 + 1]);
#pragma unroll
            for (int ei = 0; ei < 8; ++ei) {
                const int e = 2 * ei + eh;
                const ulonglong2 wA = *reinterpret_cast<const ulonglong2*>(&Wd[buf][nl][e][0][j]);
                const ulonglong2 wB = *reinterpret_cast<const ulonglong2*>(&Wd[buf][nl][e][1][j]);
#pragma unroll
                for (int i = 0; i < 2; ++i) {
                    ull a = acc[i][ei];
                    FFMA2(a, wA.x, xv[i][0].x, a);
                    FFMA2(a, wA.y, xv[i][0].y, a);
                    FFMA2(a, wB.x, xv[i][1].x, a);
                    FFMA2(a, wB.y, xv[i][1].y, a);
                    acc[i][ei] = a;
                }
            }
        }
    };

    issue(0);
    issue(1);
#pragma unroll 3
    for (int s = 0; s < NSTG; ++s) {
        cp_wait<1>();
        __syncthreads();
        if (s + 2 < NSTG) issue(s + 2); else CP_COMMIT();
        compute(s);
    }

    float* dst = g_s1 + ((blockIdx.x + blockIdx.y) & (SLOTS - 1)) * (B_ * 32);
#pragma unroll
    for (int i = 0; i < 2; ++i) {
        const int lb = (i == 0) ? lb0 : lb1;
#pragma unroll
        for (int ei = 0; ei < 8; ++ei) {
            float lo, hi;
            UNPACK2(lo, hi, acc[i][ei]);
            atomicAdd(dst + (j * 16 + 2 * ei + eh) * B_ + gbb + lb, lo + hi);
        }
    }
}

// ======================= v1 = squash(0.5 * sum_slots s1) =======================
__global__ void v1_kernel() {
    __shared__ float s[32][B_];
    const int tid = threadIdx.x;
    const int b   = tid & 255;
    const int kg  = tid >> 8;
#pragma unroll
    for (int i = 0; i < 8; ++i) {
        int k = kg * 8 + i;
        float a = 0.0f;
#pragma unroll
        for (int sl = 0; sl < SLOTS; ++sl)
            a += g_s1[sl * (B_ * 32) + k * B_ + b];
        s[k][b] = a * 0.5f;
    }
    __syncthreads();
    if (tid < 512) {
        int bb = tid >> 1, j = tid & 1;
        float sv[16], v[16];
#pragma unroll
        for (int e = 0; e < 16; ++e) sv[e] = s[j * 16 + e][bb];
        squash16(sv, v);
#pragma unroll
        for (int e = 0; e < 16; ++e) g_v1[bb * 32 + j * 16 + e] = v[e];
    }
}

// ======================= Pass 2 =======================
// 256 threads = 8 warps. Lane: j = l&1, eh = (l>>1)&1, bq = l>>2.
// Thread: capsule j, e = {4q+eh, 4q+2+eh} (q 0..3), 2 b's: lbA = w*16+bq, lbB = +8.
// Block covers 128 b; grid = (288, 2). 3 blocks/SM -> 24 warps.
#define P2_THR 256

__global__ __launch_bounds__(P2_THR, 3) void pass2_kernel(const float4* __restrict__ X,
                                                          const float4* __restrict__ Wg) {
    __shared__ float4 Wd[NBUF][NST][16][2][2];
    __shared__ float4 xs[NBUF][128][NST * 2 + 1];

    const int tid  = threadIdx.x;
    const int w    = tid >> 5;
    const int lane = tid & 31;
    const int j    = lane & 1;
    const int eh   = (lane >> 1) & 1;
    const int bq   = lane >> 2;
    const int lbA  = w * 16 + bq;
    const int lbB  = lbA + 8;
    const int gbb  = blockIdx.y * 128;
    const int bA   = gbb + lbA;
    const int bB   = gbb + lbB;
    const int nbase = blockIdx.x * NPB;

    // v1 for my e-subset, packed pairs matching u2 packing
    ull v1p[2][4];
#pragma unroll
    for (int q = 0; q < 4; ++q) {
        PACK2(v1p[0][q], g_v1[bA * 32 + j * 16 + 4 * q + eh],
                         g_v1[bA * 32 + j * 16 + 4 * q + 2 + eh]);
        PACK2(v1p[1][q], g_v1[bB * 32 + j * 16 + 4 * q + eh],
                         g_v1[bB * 32 + j * 16 + 4 * q + 2 + eh]);
    }

    ull accp[2][4];
    ull zero; PACK2(zero, 0.0f, 0.0f);
#pragma unroll
    for (int p = 0; p < 2; ++p)
#pragma unroll
        for (int q = 0; q < 4; ++q) accp[p][q] = zero;

    auto issue = [&](int s) {
        const int buf = s % NBUF;
        const int n0  = nbase + s * NST;
        if (tid < 128) STAGE_W(Wd, buf, n0, tid);
#pragma unroll
        for (int it = 0; it < 2; ++it) {   // x: 512 f4, 2 per thread
            int f = it * P2_THR + tid;
            int bl = f >> 2, q = f & 3;
            cp16(&xs[buf][bl][q],
                 X + ((size_t)(gbb + bl) * NIN_ + n0 + (q >> 1)) * 2 + (q & 1));
        }
        CP_COMMIT();
    };

    auto compute = [&](int s) {
        const int buf = s % NBUF;
#pragma unroll
        for (int nl = 0; nl < NST; ++nl) {
            const ulonglong2 xA0 = *reinterpret_cast<const ulonglong2*>(&xs[buf][lbA][nl * 2]);
            const ulonglong2 xA1 = *reinterpret_cast<const ulonglong2*>(&xs[buf][lbA][nl * 2 + 1]);
            const ulonglong2 xB0 = *reinterpret_cast<const ulonglong2*>(&xs[buf][lbB][nl * 2]);
            const ulonglong2 xB1 = *reinterpret_cast<const ulonglong2*>(&xs[buf][lbB][nl * 2 + 1]);

            ull u2A[4], u2B[4];
            ull t2A = zero, t2B = zero;
#pragma unroll
            for (int q = 0; q < 4; ++q) {
                const int e0 = 4 * q + eh, e1 = 4 * q + 2 + eh;
                const ulonglong2 w0A = *reinterpret_cast<const ulonglong2*>(&Wd[buf][nl][e0][0][j]);
                const ulonglong2 w0B = *reinterpret_cast<const ulonglong2*>(&Wd[buf][nl][e0][1][j]);
                const ulonglong2 w1A = *reinterpret_cast<const ulonglong2*>(&Wd[buf][nl][e1][0][j]);
                const ulonglong2 w1B = *reinterpret_cast<const ulonglong2*>(&Wd[buf][nl][e1][1][j]);

                ull tA0, tA1, tB0, tB1;
                FMUL2(tA0, w0A.x, xA0.x);
                FFMA2(tA0, w0A.y, xA0.y, tA0);
                FFMA2(tA0, w0B.x, xA1.x, tA0);
                FFMA2(tA0, w0B.y, xA1.y, tA0);
                FMUL2(tA1, w1A.x, xA0.x);
                FFMA2(tA1, w1A.y, xA0.y, tA1);
                FFMA2(tA1, w1B.x, xA1.x, tA1);
                FFMA2(tA1, w1B.y, xA1.y, tA1);
                FMUL2(tB0, w0A.x, xB0.x);
                FFMA2(tB0, w0A.y, xB0.y, tB0);
                FFMA2(tB0, w0B.x, xB1.x, tB0);
                FFMA2(tB0, w0B.y, xB1.y, tB0);
                FMUL2(tB1, w1A.x, xB0.x);
                FFMA2(tB1, w1A.y, xB0.y, tB1);
                FFMA2(tB1, w1B.x, xB1.x, tB1);
                FFMA2(tB1, w1B.y, xB1.y, tB1);

                float a0l, a0h, a1l, a1h, b0l, b0h, b1l, b1h;
                UNPACK2(a0l, a0h, tA0); UNPACK2(a1l, a1h, tA1);
                UNPACK2(b0l, b0h, tB0); UNPACK2(b1l, b1h, tB1);
                PACK2(u2A[q], a0l + a0h, a1l + a1h);
                PACK2(u2B[q], b0l + b0h, b1l + b1h);
                FFMA2(t2A, v1p[0][q], u2A[q], t2A);
                FFMA2(t2B, v1p[1][q], u2B[q], t2B);
            }

            float lo, hi, tA, tB;
            UNPACK2(lo, hi, t2A); tA = lo + hi;
            UNPACK2(lo, hi, t2B); tB = lo + hi;
            // reduce over eh lanes (xor 2) -> full 16-e logit for (b, j)
            tA += __shfl_xor_sync(0xffffffffu, tA, 2);
            tB += __shfl_xor_sync(0xffffffffu, tB, 2);
            // partner capsule's logit (xor 1)
            float toA = __shfl_xor_sync(0xffffffffu, tA, 1);
            float toB = __shfl_xor_sync(0xffffffffu, tB, 1);
            float cA = __fdividef(1.0f, 1.0f + __expf(toA - tA));
            float cB = __fdividef(1.0f, 1.0f + __expf(toB - tB));
            ull cdA, cdB;
            PACK2(cdA, cA, cA);
            PACK2(cdB, cB, cB);
#pragma unroll
            for (int q = 0; q < 4; ++q) {
                FFMA2(accp[0][q], cdA, u2A[q], accp[0][q]);
                FFMA2(accp[1][q], cdB, u2B[q], accp[1][q]);
            }
        }
    };

    issue(0);
    issue(1);
#pragma unroll 3
    for (int s = 0; s < NSTG; ++s) {
        cp_wait<1>();
        __syncthreads();
        if (s + 2 < NSTG) issue(s + 2); else CP_COMMIT();
        compute(s);
    }

    float* dst = g_s2 + ((blockIdx.x + blockIdx.y) & (SLOTS - 1)) * (B_ * 32);
#pragma unroll
    for (int q = 0; q < 4; ++q) {
        float lo, hi;
        UNPACK2(lo, hi, accp[0][q]);
        atomicAdd(dst + (j * 16 + 4 * q + eh) * B_ + bA,     lo);
        atomicAdd(dst + (j * 16 + 4 * q + 2 + eh) * B_ + bA, hi);
        UNPACK2(lo, hi, accp[1][q]);
        atomicAdd(dst + (j * 16 + 4 * q + eh) * B_ + bB,     lo);
        atomicAdd(dst + (j * 16 + 4 * q + 2 + eh) * B_ + bB, hi);
    }
}

// ======================= Output: v = squash(sum_slots s2) =======================
__global__ void squash_out_kernel(float* __restrict__ out) {
    __shared__ float s[32][B_];
    const int tid = threadIdx.x;
    const int b   = tid & 255;
    const int kg  = tid >> 8;
#pragma unroll
    for (int i = 0; i < 8; ++i) {
        int k = kg * 8 + i;
        float a = 0.0f;
#pragma unroll
        for (int sl = 0; sl < SLOTS; ++sl)
            a += g_s2[sl * (B_ * 32) + k * B_ + b];
        s[k][b] = a;
    }
    __syncthreads();
    if (tid < 512) {
        int bb = tid >> 1, j = tid & 1;
        float sv[16], v[16];
#pragma unroll
        for (int e = 0; e < 16; ++e) sv[e] = s[j * 16 + e][bb];
        squash16(sv, v);
#pragma unroll
        for (int e = 0; e < 16; ++e) out[bb * 32 + j * 16 + e] = v[e];
    }
}

extern "C" void kernel_launch(void* const* d_in, const int* in_sizes, int n_in,
                              void* d_out, int out_size) {
    const float4* X = (const float4*)d_in[0];   // x: [256, 6912, 8] f32
    const float4* W = (const float4*)d_in[1];   // W: [2, 6912, 16, 8] f32
    float* out = (float*)d_out;                 // v: [256, 2, 16] f32

    zero_kernel<<<(SLOTS * B_ * 32 + 255) / 256, 256>>>();

    dim3 g1(NIN_ / NPB, B_ / 128);   // 288 x 2
    pass1_kernel<<<g1, P1_THR>>>(X, W);

    v1_kernel<<<1, 1024>>>();

    dim3 g2(NIN_ / NPB, B_ / 128);   // 288 x 2
    pass2_kernel<<<g2, P2_THR>>>(X, W);

    squash_out_kernel<<<1, 1024>>>(out);
}

// round 14
// speedup vs baseline: 1.2199x; 1.2199x over previous
#include <cuda_runtime.h>
#include <math.h>
#include <stdint.h>

#define B_    256
#define NIN_  6912
#define SLOTS 8

typedef unsigned long long ull;

// ---------------- packed f32 helpers (SIMT pass2) ----------------
#define FFMA2(d, a, b, c) \
    asm("fma.rn.f32x2 %0, %1, %2, %3;" : "=l"(d) : "l"(a), "l"(b), "l"(c))
#define FMUL2(d, a, b) \
    asm("mul.rn.f32x2 %0, %1, %2;" : "=l"(d) : "l"(a), "l"(b))
#define PACK2(d, lo, hi) \
    asm("mov.b64 %0, {%1, %2};" : "=l"(d) : "f"(lo), "f"(hi))
#define UNPACK2(lo, hi, v) \
    asm("mov.b64 {%0, %1}, %2;" : "=f"(lo), "=f"(hi) : "l"(v))

// ---------------- cp.async ----------------
__device__ __forceinline__ uint32_t s2u(const void* p) {
    return (uint32_t)__cvta_generic_to_shared(p);
}
__device__ __forceinline__ void cp16(const void* sdst, const void* gsrc) {
    asm volatile("cp.async.cg.shared.global [%0], [%1], 16;"
                 :: "r"(s2u(sdst)), "l"(gsrc) : "memory");
}
#define CP_COMMIT() asm volatile("cp.async.commit_group;" ::: "memory")
template <int N>
__device__ __forceinline__ void cp_wait() {
    asm volatile("cp.async.wait_group %0;" :: "n"(N) : "memory");
}

// ---------------- tf32 mma helpers ----------------
__device__ __forceinline__ void tf32_split(float x, uint32_t& hi, uint32_t& lo) {
    asm("cvt.rna.tf32.f32 %0, %1;" : "=r"(hi) : "f"(x));
    float r = x - __uint_as_float(hi);
    asm("cvt.rna.tf32.f32 %0, %1;" : "=r"(lo) : "f"(r));
}
__device__ __forceinline__ void mma_tf32(float* d, const uint32_t* a,
                                         uint32_t b0, uint32_t b1) {
    asm volatile(
        "mma.sync.aligned.m16n8k8.row.col.f32.tf32.tf32.f32 "
        "{%0,%1,%2,%3}, {%4,%5,%6,%7}, {%8,%9}, {%0,%1,%2,%3};"
        : "+f"(d[0]), "+f"(d[1]), "+f"(d[2]), "+f"(d[3])
        : "r"(a[0]), "r"(a[1]), "r"(a[2]), "r"(a[3]), "r"(b0), "r"(b1));
}

// ---------------- scratch ----------------
__device__ float g_s1[SLOTS * B_ * 32];
__device__ float g_s2[SLOTS * B_ * 32];
__device__ __align__(16) float g_v1[B_ * 32];

__global__ void zero_kernel() {
    int i = blockIdx.x * blockDim.x + threadIdx.x;
    if (i < SLOTS * B_ * 32) { g_s1[i] = 0.0f; g_s2[i] = 0.0f; }
}

__device__ __forceinline__ void squash16(const float* s, float* v) {
    float n2 = 0.0f;
#pragma unroll
    for (int e = 0; e < 16; ++e) n2 = fmaf(s[e], s[e], n2);
    float f = n2 / ((1.0f + n2) * sqrtf(n2 + 1e-9f));
#pragma unroll
    for (int e = 0; e < 16; ++e) v[e] = s[e] * f;
}

// =================================================================
// Pass 1 (mma.sync tf32): S1[128b-tile, 32] += X_tile @ W_tile^T
// Block: 256 thr = 8 warps, 128 b, 48 n (12 stages x 4 n, K=32/stage).
// Warp w owns m-tile w (16 b) x all 4 n-tiles (32 outputs).
// smem (dynamic): xs[3][128][36] f32, Wt[3][32][36] f32.
// =================================================================
#define NPB1  48
#define NST1  4
#define NSTG1 12
#define NBUF1 3

#define XS_STRIDE 18432              // 128*36*4 bytes per buffer
#define WT_OFF    (3 * XS_STRIDE)    // 55296
#define WT_STRIDE 4608               // 32*36*4
#define SMEM_TC   (WT_OFF + 3 * WT_STRIDE)   // 69120

__global__ __launch_bounds__(256, 2) void pass1_tc(const float4* __restrict__ X,
                                                   const float4* __restrict__ Wg) {
    extern __shared__ char sm[];
    const int tid  = threadIdx.x;
    const int wid  = tid >> 5;
    const int lane = tid & 31;
    const int bB   = blockIdx.y * 128;
    const int nbase = blockIdx.x * NPB1;

    float acc[4][4];                    // [ntile][frag reg]
#pragma unroll
    for (int nt = 0; nt < 4; ++nt)
#pragma unroll
        for (int i = 0; i < 4; ++i) acc[nt][i] = 0.0f;

    auto issue = [&](int s) {
        const int buf = s % NBUF1;
        const int n0  = nbase + s * NST1;
        char* xd = sm + buf * XS_STRIDE;
        char* wd = sm + WT_OFF + buf * WT_STRIDE;
#pragma unroll
        for (int it = 0; it < 4; ++it) {       // x: 1024 f4, 4/thread
            int f = it * 256 + tid;
            int bl = f >> 3, q = f & 7;        // q: f4 within 32-f32 row
            cp16(xd + bl * 144 + q * 16,
                 X + ((size_t)(bB + bl) * NIN_ + n0) * 2 + q);
        }
        {   // W: 256 f4, 1/thread. Row = output (j*16+e), 36-f32 stride.
            int j = tid >> 7, e = (tid >> 3) & 15, nl = (tid >> 1) & 3, dh = tid & 1;
            cp16(wd + ((j * 16 + e) * 36 + nl * 8 + dh * 4) * 4,
                 Wg + ((size_t)(j * NIN_ + n0 + nl) * 16 + e) * 2 + dh);
        }
        CP_COMMIT();
    };

    auto compute = [&](int s) {
        const int buf = s % NBUF1;
        const float* xb = (const float*)(sm + buf * XS_STRIDE);
        const float* wb = (const float*)(sm + WT_OFF + buf * WT_STRIDE);
        const int r  = wid * 16 + (lane >> 2);   // A row (local b)
        const int cc = lane & 3;                 // frag col base
#pragma unroll
        for (int kt = 0; kt < 4; ++kt) {
            const int k0 = kt * 8 + cc;
            float a0 = xb[r * 36 + k0];
            float a1 = xb[(r + 8) * 36 + k0];
            float a2 = xb[r * 36 + k0 + 4];
            float a3 = xb[(r + 8) * 36 + k0 + 4];
            uint32_t ah[4], al[4];
            tf32_split(a0, ah[0], al[0]);
            tf32_split(a1, ah[1], al[1]);
            tf32_split(a2, ah[2], al[2]);
            tf32_split(a3, ah[3], al[3]);
#pragma unroll
            for (int nt = 0; nt < 4; ++nt) {
                float b0 = wb[(nt * 8 + (lane >> 2)) * 36 + kt * 8 + cc];
                float b1 = wb[(nt * 8 + (lane >> 2)) * 36 + kt * 8 + cc + 4];
                uint32_t bh0, bl0, bh1, bl1;
                tf32_split(b0, bh0, bl0);
                tf32_split(b1, bh1, bl1);
                mma_tf32(acc[nt], ah, bh0, bh1);   // hi*hi
                mma_tf32(acc[nt], ah, bl0, bl1);   // hi*lo
                mma_tf32(acc[nt], al, bh0, bh1);   // lo*hi
            }
        }
    };

    issue(0);
    issue(1);
#pragma unroll 3
    for (int s = 0; s < NSTG1; ++s) {
        cp_wait<1>();
        __syncthreads();
        if (s + 2 < NSTG1) issue(s + 2); else CP_COMMIT();
        compute(s);
    }

    // Epilogue: D frag c0:(row=l/4, col=2*(l%4)), c1:+1col, c2/c3:+8row
    float* dst = g_s1 + (blockIdx.x & (SLOTS - 1)) * (B_ * 32);
    const int r0 = bB + wid * 16 + (lane >> 2);
    const int c0base = (lane & 3) * 2;
#pragma unroll
    for (int nt = 0; nt < 4; ++nt) {
        const int col = nt * 8 + c0base;
        atomicAdd(dst + col * B_ + r0,           acc[nt][0]);
        atomicAdd(dst + (col + 1) * B_ + r0,     acc[nt][1]);
        atomicAdd(dst + col * B_ + r0 + 8,       acc[nt][2]);
        atomicAdd(dst + (col + 1) * B_ + r0 + 8, acc[nt][3]);
    }
}

// ======================= v1 = squash(0.5 * sum_slots s1) =======================
__global__ void v1_kernel() {
    __shared__ float s[32][B_];
    const int tid = threadIdx.x;
    const int b   = tid & 255;
    const int kg  = tid >> 8;
#pragma unroll
    for (int i = 0; i < 8; ++i) {
        int k = kg * 8 + i;
        float a = 0.0f;
#pragma unroll
        for (int sl = 0; sl < SLOTS; ++sl)
            a += g_s1[sl * (B_ * 32) + k * B_ + b];
        s[k][b] = a * 0.5f;
    }
    __syncthreads();
    if (tid < 512) {
        int bb = tid >> 1, j = tid & 1;
        float sv[16], v[16];
#pragma unroll
        for (int e = 0; e < 16; ++e) sv[e] = s[j * 16 + e][bb];
        squash16(sv, v);
#pragma unroll
        for (int e = 0; e < 16; ++e) g_v1[bb * 32 + j * 16 + e] = v[e];
    }
}

// ======================= Pass 2 (round-7 SIMT, best known) =======================
#define NPB   24
#define NST   2
#define NSTG  (NPB / NST)
#define NBUF  3
#define P2_THR 256

__global__ __launch_bounds__(P2_THR, 2) void pass2_kernel(const float4* __restrict__ X,
                                                          const float4* __restrict__ Wg) {
    __shared__ float4 Wd[NBUF][NST][16][2][2];
    __shared__ float4 xs[NBUF][128][NST * 2 + 1];

    const int tid   = threadIdx.x;
    const int j     = tid & 1;
    const int bl    = tid >> 1;
    const int gbb   = blockIdx.y * 128;
    const int b     = gbb + bl;
    const int nbase = blockIdx.x * NPB;

    ull v1p[8];
    {
        const float4* vp = reinterpret_cast<const float4*>(g_v1 + b * 32 + j * 16);
#pragma unroll
        for (int q = 0; q < 4; ++q) {
            float4 v = vp[q];
            PACK2(v1p[2 * q],     v.x, v.y);
            PACK2(v1p[2 * q + 1], v.z, v.w);
        }
    }

    ull accp[8];
    ull zero; PACK2(zero, 0.0f, 0.0f);
#pragma unroll
    for (int q = 0; q < 8; ++q) accp[q] = zero;

    auto issue = [&](int s) {
        const int buf = s % NBUF;
        const int n0  = nbase + s * NST;
        if (tid < 128) {
            int f  = tid;
            int jj = f & 1, h = (f >> 1) & 1, e = (f >> 2) & 15, nl = (f >> 6) & 1;
            cp16(&Wd[buf][nl][e][h][jj],
                 Wg + ((size_t)(jj * NIN_ + n0 + nl) * 16 + e) * 2 + h);
        }
#pragma unroll
        for (int it = 0; it < 2; ++it) {
            int f = it * P2_THR + tid;
            int b2 = f >> 2, q = f & 3, nl = q >> 1, h = q & 1;
            cp16(&xs[buf][b2][q],
                 X + ((size_t)(gbb + b2) * NIN_ + n0 + nl) * 2 + h);
        }
        CP_COMMIT();
    };

    auto compute = [&](int s) {
        const int buf = s % NBUF;
        ull up[NST][8];
        float tj[NST];
#pragma unroll
        for (int nl = 0; nl < NST; ++nl) {
            const ulonglong2 x0 = *reinterpret_cast<const ulonglong2*>(&xs[buf][bl][nl * 2]);
            const ulonglong2 x1 = *reinterpret_cast<const ulonglong2*>(&xs[buf][bl][nl * 2 + 1]);
            ull t2 = zero;
#pragma unroll
            for (int q = 0; q < 8; ++q) {
                const int e0 = 2 * q, e1 = 2 * q + 1;
                const ulonglong2 wA0 = *reinterpret_cast<const ulonglong2*>(&Wd[buf][nl][e0][0][j]);
                const ulonglong2 wB0 = *reinterpret_cast<const ulonglong2*>(&Wd[buf][nl][e0][1][j]);
                const ulonglong2 wA1 = *reinterpret_cast<const ulonglong2*>(&Wd[buf][nl][e1][0][j]);
                const ulonglong2 wB1 = *reinterpret_cast<const ulonglong2*>(&Wd[buf][nl][e1][1][j]);
                ull ta, tb;
                FMUL2(ta, wA0.x, x0.x);
                FFMA2(ta, wA0.y, x0.y, ta);
                FFMA2(ta, wB0.x, x1.x, ta);
                FFMA2(ta, wB0.y, x1.y, ta);
                FMUL2(tb, wA1.x, x0.x);
                FFMA2(tb, wA1.y, x0.y, tb);
                FFMA2(tb, wB1.x, x1.x, tb);
                FFMA2(tb, wB1.y, x1.y, tb);
                float alo, ahi, blo2, bhi2;
                UNPACK2(alo, ahi, ta);
                UNPACK2(blo2, bhi2, tb);
                ull u;
                PACK2(u, alo + ahi, blo2 + bhi2);
                up[nl][q] = u;
                FFMA2(t2, v1p[q], u, t2);
            }
            float tlo, thi;
            UNPACK2(tlo, thi, t2);
            tj[nl] = tlo + thi;
        }
        float c[NST];
#pragma unroll
        for (int nl = 0; nl < NST; ++nl) {
            float to = __shfl_xor_sync(0xffffffffu, tj[nl], 1);
            c[nl] = __fdividef(1.0f, 1.0f + __expf(to - tj[nl]));
        }
#pragma unroll
        for (int nl = 0; nl < NST; ++nl) {
            ull cd; PACK2(cd, c[nl], c[nl]);
#pragma unroll
            for (int q = 0; q < 8; ++q)
                FFMA2(accp[q], cd, up[nl][q], accp[q]);
        }
    };

    issue(0);
    issue(1);
#pragma unroll 3
    for (int s = 0; s < NSTG; ++s) {
        cp_wait<1>();
        __syncthreads();
        compute(s);
        if (s + 2 < NSTG) issue(s + 2); else CP_COMMIT();
    }

    float* dst = g_s2 + (blockIdx.x & (SLOTS - 1)) * (B_ * 32);
#pragma unroll
    for (int q = 0; q < 8; ++q) {
        float lo, hi;
        UNPACK2(lo, hi, accp[q]);
        atomicAdd(dst + (j * 16 + 2 * q) * B_ + b,     lo);
        atomicAdd(dst + (j * 16 + 2 * q + 1) * B_ + b, hi);
    }
}

// ======================= Output: v = squash(sum_slots s2) =======================
__global__ void squash_out_kernel(float* __restrict__ out) {
    __shared__ float s[32][B_];
    const int tid = threadIdx.x;
    const int b   = tid & 255;
    const int kg  = tid >> 8;
#pragma unroll
    for (int i = 0; i < 8; ++i) {
        int k = kg * 8 + i;
        float a = 0.0f;
#pragma unroll
        for (int sl = 0; sl < SLOTS; ++sl)
            a += g_s2[sl * (B_ * 32) + k * B_ + b];
        s[k][b] = a;
    }
    __syncthreads();
    if (tid < 512) {
        int bb = tid >> 1, j = tid & 1;
        float sv[16], v[16];
#pragma unroll
        for (int e = 0; e < 16; ++e) sv[e] = s[j * 16 + e][bb];
        squash16(sv, v);
#pragma unroll
        for (int e = 0; e < 16; ++e) out[bb * 32 + j * 16 + e] = v[e];
    }
}

extern "C" void kernel_launch(void* const* d_in, const int* in_sizes, int n_in,
                              void* d_out, int out_size) {
    const float4* X = (const float4*)d_in[0];   // x: [256, 6912, 8] f32
    const float4* W = (const float4*)d_in[1];   // W: [2, 6912, 16, 8] f32
    float* out = (float*)d_out;                 // v: [256, 2, 16] f32

    cudaFuncSetAttribute(pass1_tc, cudaFuncAttributeMaxDynamicSharedMemorySize, SMEM_TC);

    zero_kernel<<<(SLOTS * B_ * 32 + 255) / 256, 256>>>();

    dim3 g1(NIN_ / NPB1, 2);               // 144 x 2 = 288 blocks
    pass1_tc<<<g1, 256, SMEM_TC>>>(X, W);

    v1_kernel<<<1, 1024>>>();

    dim3 g2(NIN_ / NPB, B_ / 128);         // 288 blocks
    pass2_kernel<<<g2, P2_THR>>>(X, W);

    squash_out_kernel<<<1, 1024>>>(out);
}

// round 15
// speedup vs baseline: 1.4807x; 1.2138x over previous
#include <cuda_runtime.h>
#include <math.h>
#include <stdint.h>

#define B_    256
#define NIN_  6912
#define SLOTS 8

typedef unsigned long long ull;

// ---------------- cp.async ----------------
__device__ __forceinline__ uint32_t s2u(const void* p) {
    return (uint32_t)__cvta_generic_to_shared(p);
}
__device__ __forceinline__ void cp16(const void* sdst, const void* gsrc) {
    asm volatile("cp.async.cg.shared.global [%0], [%1], 16;"
                 :: "r"(s2u(sdst)), "l"(gsrc) : "memory");
}
#define CP_COMMIT() asm volatile("cp.async.commit_group;" ::: "memory")
template <int N>
__device__ __forceinline__ void cp_wait() {
    asm volatile("cp.async.wait_group %0;" :: "n"(N) : "memory");
}

// ---------------- tf32 mma (pass1) ----------------
__device__ __forceinline__ void tf32_split(float x, uint32_t& hi, uint32_t& lo) {
    asm("cvt.rna.tf32.f32 %0, %1;" : "=r"(hi) : "f"(x));
    float r = x - __uint_as_float(hi);
    asm("cvt.rna.tf32.f32 %0, %1;" : "=r"(lo) : "f"(r));
}
__device__ __forceinline__ void mma_tf32(float* d, const uint32_t* a,
                                         uint32_t b0, uint32_t b1) {
    asm volatile(
        "mma.sync.aligned.m16n8k8.row.col.f32.tf32.tf32.f32 "
        "{%0,%1,%2,%3}, {%4,%5,%6,%7}, {%8,%9}, {%0,%1,%2,%3};"
        : "+f"(d[0]), "+f"(d[1]), "+f"(d[2]), "+f"(d[3])
        : "r"(a[0]), "r"(a[1]), "r"(a[2]), "r"(a[3]), "r"(b0), "r"(b1));
}

// ---------------- bf16 mma (pass2) ----------------
// split float2 -> hi bf16x2 + lo bf16x2 (residual)
__device__ __forceinline__ void bf16_split2(float vx, float vy,
                                            uint32_t& hi2, uint32_t& lo2) {
    asm("cvt.rn.bf16x2.f32 %0, %1, %2;" : "=r"(hi2) : "f"(vy), "f"(vx));
    float h0 = __uint_as_float(hi2 << 16);
    float h1 = __uint_as_float(hi2 & 0xffff0000u);
    float r0 = vx - h0, r1 = vy - h1;
    asm("cvt.rn.bf16x2.f32 %0, %1, %2;" : "=r"(lo2) : "f"(r1), "f"(r0));
}
__device__ __forceinline__ void mma_bf16_z(float* d, const uint32_t* a,
                                           uint32_t b0, uint32_t b1) {
    asm volatile(
        "mma.sync.aligned.m16n8k16.row.col.f32.bf16.bf16.f32 "
        "{%0,%1,%2,%3}, {%4,%5,%6,%7}, {%8,%9}, {%10,%10,%10,%10};"
        : "=f"(d[0]), "=f"(d[1]), "=f"(d[2]), "=f"(d[3])
        : "r"(a[0]), "r"(a[1]), "r"(a[2]), "r"(a[3]), "r"(b0), "r"(b1), "f"(0.0f));
}
__device__ __forceinline__ void mma_bf16(float* d, const uint32_t* a,
                                         uint32_t b0, uint32_t b1) {
    asm volatile(
        "mma.sync.aligned.m16n8k16.row.col.f32.bf16.bf16.f32 "
        "{%0,%1,%2,%3}, {%4,%5,%6,%7}, {%8,%9}, {%0,%1,%2,%3};"
        : "+f"(d[0]), "+f"(d[1]), "+f"(d[2]), "+f"(d[3])
        : "r"(a[0]), "r"(a[1]), "r"(a[2]), "r"(a[3]), "r"(b0), "r"(b1));
}

// ---------------- scratch ----------------
__device__ float g_s1[SLOTS * B_ * 32];
__device__ float g_s2[SLOTS * B_ * 32];
__device__ __align__(16) float g_v1[B_ * 32];

__global__ void zero_kernel() {
    int i = blockIdx.x * blockDim.x + threadIdx.x;
    if (i < SLOTS * B_ * 32) { g_s1[i] = 0.0f; g_s2[i] = 0.0f; }
}

__device__ __forceinline__ void squash16(const float* s, float* v) {
    float n2 = 0.0f;
#pragma unroll
    for (int e = 0; e < 16; ++e) n2 = fmaf(s[e], s[e], n2);
    float f = n2 / ((1.0f + n2) * sqrtf(n2 + 1e-9f));
#pragma unroll
    for (int e = 0; e < 16; ++e) v[e] = s[e] * f;
}

// =================================================================
// Pass 1 (mma.sync tf32 3x): identical to round-14 passing version.
// =================================================================
#define NPB1  48
#define NST1  4
#define NSTG1 12
#define NBUF1 3

#define XS_STRIDE 18432
#define WT_OFF    (3 * XS_STRIDE)
#define WT_STRIDE 4608
#define SMEM_TC   (WT_OFF + 3 * WT_STRIDE)

__global__ __launch_bounds__(256, 2) void pass1_tc(const float4* __restrict__ X,
                                                   const float4* __restrict__ Wg) {
    extern __shared__ char sm[];
    const int tid  = threadIdx.x;
    const int wid  = tid >> 5;
    const int lane = tid & 31;
    const int bB   = blockIdx.y * 128;
    const int nbase = blockIdx.x * NPB1;

    float acc[4][4];
#pragma unroll
    for (int nt = 0; nt < 4; ++nt)
#pragma unroll
        for (int i = 0; i < 4; ++i) acc[nt][i] = 0.0f;

    auto issue = [&](int s) {
        const int buf = s % NBUF1;
        const int n0  = nbase + s * NST1;
        char* xd = sm + buf * XS_STRIDE;
        char* wd = sm + WT_OFF + buf * WT_STRIDE;
#pragma unroll
        for (int it = 0; it < 4; ++it) {
            int f = it * 256 + tid;
            int bl = f >> 3, q = f & 7;
            cp16(xd + bl * 144 + q * 16,
                 X + ((size_t)(bB + bl) * NIN_ + n0) * 2 + q);
        }
        {
            int j = tid >> 7, e = (tid >> 3) & 15, nl = (tid >> 1) & 3, dh = tid & 1;
            cp16(wd + ((j * 16 + e) * 36 + nl * 8 + dh * 4) * 4,
                 Wg + ((size_t)(j * NIN_ + n0 + nl) * 16 + e) * 2 + dh);
        }
        CP_COMMIT();
    };

    auto compute = [&](int s) {
        const int buf = s % NBUF1;
        const float* xb = (const float*)(sm + buf * XS_STRIDE);
        const float* wb = (const float*)(sm + WT_OFF + buf * WT_STRIDE);
        const int r  = wid * 16 + (lane >> 2);
        const int cc = lane & 3;
#pragma unroll
        for (int kt = 0; kt < 4; ++kt) {
            const int k0 = kt * 8 + cc;
            float a0 = xb[r * 36 + k0];
            float a1 = xb[(r + 8) * 36 + k0];
            float a2 = xb[r * 36 + k0 + 4];
            float a3 = xb[(r + 8) * 36 + k0 + 4];
            uint32_t ah[4], al[4];
            tf32_split(a0, ah[0], al[0]);
            tf32_split(a1, ah[1], al[1]);
            tf32_split(a2, ah[2], al[2]);
            tf32_split(a3, ah[3], al[3]);
#pragma unroll
            for (int nt = 0; nt < 4; ++nt) {
                float b0 = wb[(nt * 8 + (lane >> 2)) * 36 + kt * 8 + cc];
                float b1 = wb[(nt * 8 + (lane >> 2)) * 36 + kt * 8 + cc + 4];
                uint32_t bh0, bl0, bh1, bl1;
                tf32_split(b0, bh0, bl0);
                tf32_split(b1, bh1, bl1);
                mma_tf32(acc[nt], ah, bh0, bh1);
                mma_tf32(acc[nt], ah, bl0, bl1);
                mma_tf32(acc[nt], al, bh0, bh1);
            }
        }
    };

    issue(0);
    issue(1);
#pragma unroll 3
    for (int s = 0; s < NSTG1; ++s) {
        cp_wait<1>();
        __syncthreads();
        if (s + 2 < NSTG1) issue(s + 2); else CP_COMMIT();
        compute(s);
    }

    float* dst = g_s1 + (blockIdx.x & (SLOTS - 1)) * (B_ * 32);
    const int r0 = bB + wid * 16 + (lane >> 2);
    const int c0base = (lane & 3) * 2;
#pragma unroll
    for (int nt = 0; nt < 4; ++nt) {
        const int col = nt * 8 + c0base;
        atomicAdd(dst + col * B_ + r0,           acc[nt][0]);
        atomicAdd(dst + (col + 1) * B_ + r0,     acc[nt][1]);
        atomicAdd(dst + col * B_ + r0 + 8,       acc[nt][2]);
        atomicAdd(dst + (col + 1) * B_ + r0 + 8, acc[nt][3]);
    }
}

// ======================= v1 = squash(0.5 * sum_slots s1) =======================
__global__ void v1_kernel() {
    __shared__ float s[32][B_];
    const int tid = threadIdx.x;
    const int b   = tid & 255;
    const int kg  = tid >> 8;
#pragma unroll
    for (int i = 0; i < 8; ++i) {
        int k = kg * 8 + i;
        float a = 0.0f;
#pragma unroll
        for (int sl = 0; sl < SLOTS; ++sl)
            a += g_s1[sl * (B_ * 32) + k * B_ + b];
        s[k][b] = a * 0.5f;
    }
    __syncthreads();
    if (tid < 512) {
        int bb = tid >> 1, j = tid & 1;
        float sv[16], v[16];
#pragma unroll
        for (int e = 0; e < 16; ++e) sv[e] = s[j * 16 + e][bb];
        squash16(sv, v);
#pragma unroll
        for (int e = 0; e < 16; ++e) g_v1[bb * 32 + j * 16 + e] = v[e];
    }
}

// =================================================================
// Pass 2 (mma.sync bf16, K-half hi/lo): per n, u[16b x 32] via 8 MMAs,
// routing in D fragments. 256 thr, 128 b, 48 n (12 stages x 4 n).
// W pre-split per stage into bf16x2 smem (Whi/Wlo).
// =================================================================
#define NPB2  48
#define NST2  4
#define NSTG2 12

#define WHI_OFF  (WT_OFF + 3 * WT_STRIDE)   // 69120
#define WLO_OFF  (WHI_OFF + 2048)
#define SMEM_TC2 (WLO_OFF + 2048)           // 73216

__global__ __launch_bounds__(256, 2) void pass2_tc(const float4* __restrict__ X,
                                                   const float4* __restrict__ Wg) {
    extern __shared__ char sm[];
    const int tid  = threadIdx.x;
    const int wid  = tid >> 5;
    const int lane = tid & 31;
    const int cc   = lane & 3;
    const int rr   = lane >> 2;
    const int bB   = blockIdx.y * 128;
    const int nbase = blockIdx.x * NPB2;

    uint32_t* Whi = (uint32_t*)(sm + WHI_OFF);
    uint32_t* Wlo = (uint32_t*)(sm + WLO_OFF);

    // v1 for this thread's fragment footprint: rows r0, r0+8; cols nt*8+2cc+{0,1}
    const int r0 = bB + wid * 16 + rr;
    float v1f[2][4][2];
#pragma unroll
    for (int i = 0; i < 2; ++i)
#pragma unroll
        for (int nt = 0; nt < 4; ++nt) {
            v1f[i][nt][0] = g_v1[(r0 + i * 8) * 32 + nt * 8 + 2 * cc];
            v1f[i][nt][1] = g_v1[(r0 + i * 8) * 32 + nt * 8 + 2 * cc + 1];
        }

    float sacc[4][4];
#pragma unroll
    for (int nt = 0; nt < 4; ++nt)
#pragma unroll
        for (int i = 0; i < 4; ++i) sacc[nt][i] = 0.0f;

    auto issue = [&](int s) {    // identical staging to pass1
        const int buf = s % NBUF1;
        const int n0  = nbase + s * NST2;
        char* xd = sm + buf * XS_STRIDE;
        char* wd = sm + WT_OFF + buf * WT_STRIDE;
#pragma unroll
        for (int it = 0; it < 4; ++it) {
            int f = it * 256 + tid;
            int bl = f >> 3, q = f & 7;
            cp16(xd + bl * 144 + q * 16,
                 X + ((size_t)(bB + bl) * NIN_ + n0) * 2 + q);
        }
        {
            int j = tid >> 7, e = (tid >> 3) & 15, nl = (tid >> 1) & 3, dh = tid & 1;
            cp16(wd + ((j * 16 + e) * 36 + nl * 8 + dh * 4) * 4,
                 Wg + ((size_t)(j * NIN_ + n0 + nl) * 16 + e) * 2 + dh);
        }
        CP_COMMIT();
    };

    auto convertW = [&](int s) {   // f32 stage W -> bf16 hi/lo (shared once)
        const int buf = s % NBUF1;
        const float* wb = (const float*)(sm + WT_OFF + buf * WT_STRIDE);
#pragma unroll
        for (int i = 0; i < 2; ++i) {
            int u = tid * 2 + i;               // 0..511
            int n = u >> 7, out = (u >> 2) & 31, c = u & 3;
            float w0 = wb[out * 36 + n * 8 + 2 * c];
            float w1 = wb[out * 36 + n * 8 + 2 * c + 1];
            uint32_t h, l;
            bf16_split2(w0, w1, h, l);
            Whi[n * 128 + out * 4 + c] = h;
            Wlo[n * 128 + out * 4 + c] = l;
        }
    };

    auto compute = [&](int s) {
        const int buf = s % NBUF1;
        const float* xb = (const float*)(sm + buf * XS_STRIDE);
        const int rA = wid * 16 + rr;
#pragma unroll
        for (int nl = 0; nl < NST2; ++nl) {
            // A fragment: hi in k0-7, lo in k8-15
            float x0 = xb[rA * 36 + nl * 8 + 2 * cc];
            float x1 = xb[rA * 36 + nl * 8 + 2 * cc + 1];
            float y0 = xb[(rA + 8) * 36 + nl * 8 + 2 * cc];
            float y1 = xb[(rA + 8) * 36 + nl * 8 + 2 * cc + 1];
            uint32_t a[4];
            bf16_split2(x0, x1, a[0], a[2]);
            bf16_split2(y0, y1, a[1], a[3]);

            float u[4][4];
#pragma unroll
            for (int nt = 0; nt < 4; ++nt) {
                uint32_t bh = Whi[nl * 128 + (nt * 8 + rr) * 4 + cc];
                uint32_t bl = Wlo[nl * 128 + (nt * 8 + rr) * 4 + cc];
                mma_bf16_z(u[nt], a, bh, bh);    // (Ahi+Alo) . Bhi
                mma_bf16(u[nt], a, bl, bl);      // + (Ahi+Alo) . Blo
            }

            // logit partials: t[row][j], j = nt>>1
            float t00 = 0.f, t01 = 0.f, t10 = 0.f, t11 = 0.f;
#pragma unroll
            for (int nt = 0; nt < 4; ++nt) {
                float p0 = fmaf(v1f[0][nt][0], u[nt][0],
                                v1f[0][nt][1] * u[nt][1]);
                float p1 = fmaf(v1f[1][nt][0], u[nt][2],
                                v1f[1][nt][1] * u[nt][3]);
                if (nt < 2) { t00 += p0; t10 += p1; }
                else        { t01 += p0; t11 += p1; }
            }
            // reduce over the 4 lanes of the col group (xor 1, 2)
#pragma unroll
            for (int st = 1; st <= 2; st <<= 1) {
                t00 += __shfl_xor_sync(0xffffffffu, t00, st);
                t01 += __shfl_xor_sync(0xffffffffu, t01, st);
                t10 += __shfl_xor_sync(0xffffffffu, t10, st);
                t11 += __shfl_xor_sync(0xffffffffu, t11, st);
            }
            // softmax over j for rows rA, rA+8
            float c0a = __fdividef(1.0f, 1.0f + __expf(t01 - t00));
            float c0b = __fdividef(1.0f, 1.0f + __expf(t11 - t10));
            float c1a = 1.0f - c0a;
            float c1b = 1.0f - c0b;
#pragma unroll
            for (int nt = 0; nt < 4; ++nt) {
                float ca = (nt < 2) ? c0a : c1a;   // row rA
                float cb = (nt < 2) ? c0b : c1b;   // row rA+8
                sacc[nt][0] = fmaf(ca, u[nt][0], sacc[nt][0]);
                sacc[nt][1] = fmaf(ca, u[nt][1], sacc[nt][1]);
                sacc[nt][2] = fmaf(cb, u[nt][2], sacc[nt][2]);
                sacc[nt][3] = fmaf(cb, u[nt][3], sacc[nt][3]);
            }
        }
    };

    issue(0);
    issue(1);
#pragma unroll 3
    for (int s = 0; s < NSTG2; ++s) {
        cp_wait<1>();
        __syncthreads();
        convertW(s);
        __syncthreads();
        if (s + 2 < NSTG2) issue(s + 2); else CP_COMMIT();
        compute(s);
    }

    float* dst = g_s2 + (blockIdx.x & (SLOTS - 1)) * (B_ * 32);
    const int c0base = cc * 2;
#pragma unroll
    for (int nt = 0; nt < 4; ++nt) {
        const int col = nt * 8 + c0base;
        atomicAdd(dst + col * B_ + r0,           sacc[nt][0]);
        atomicAdd(dst + (col + 1) * B_ + r0,     sacc[nt][1]);
        atomicAdd(dst + col * B_ + r0 + 8,       sacc[nt][2]);
        atomicAdd(dst + (col + 1) * B_ + r0 + 8, sacc[nt][3]);
    }
}

// ======================= Output: v = squash(sum_slots s2) =======================
__global__ void squash_out_kernel(float* __restrict__ out) {
    __shared__ float s[32][B_];
    const int tid = threadIdx.x;
    const int b   = tid & 255;
    const int kg  = tid >> 8;
#pragma unroll
    for (int i = 0; i < 8; ++i) {
        int k = kg * 8 + i;
        float a = 0.0f;
#pragma unroll
        for (int sl = 0; sl < SLOTS; ++sl)
            a += g_s2[sl * (B_ * 32) + k * B_ + b];
        s[k][b] = a;
    }
    __syncthreads();
    if (tid < 512) {
        int bb = tid >> 1, j = tid & 1;
        float sv[16], v[16];
#pragma unroll
        for (int e = 0; e < 16; ++e) sv[e] = s[j * 16 + e][bb];
        squash16(sv, v);
#pragma unroll
        for (int e = 0; e < 16; ++e) out[bb * 32 + j * 16 + e] = v[e];
    }
}

extern "C" void kernel_launch(void* const* d_in, const int* in_sizes, int n_in,
                              void* d_out, int out_size) {
    const float4* X = (const float4*)d_in[0];   // x: [256, 6912, 8] f32
    const float4* W = (const float4*)d_in[1];   // W: [2, 6912, 16, 8] f32
    float* out = (float*)d_out;                 // v: [256, 2, 16] f32

    cudaFuncSetAttribute(pass1_tc, cudaFuncAttributeMaxDynamicSharedMemorySize, SMEM_TC);
    cudaFuncSetAttribute(pass2_tc, cudaFuncAttributeMaxDynamicSharedMemorySize, SMEM_TC2);

    zero_kernel<<<(SLOTS * B_ * 32 + 255) / 256, 256>>>();

    dim3 g1(NIN_ / NPB1, 2);               // 144 x 2
    pass1_tc<<<g1, 256, SMEM_TC>>>(X, W);

    v1_kernel<<<1, 1024>>>();

    dim3 g2(NIN_ / NPB2, 2);               // 144 x 2
    pass2_tc<<<g2, 256, SMEM_TC2>>>(X, W);

    squash_out_kernel<<<1, 1024>>>(out);
}